// round 1
// baseline (speedup 1.0000x reference)
#include <cuda_runtime.h>
#include <stdint.h>

#define NTOK 8192
#define DM   2048
#define NE   8
#define FE   1024
#define FS   2048

// ---------------- scratch (device globals; no allocation) ----------------
__device__ float g_comb[NTOK * NE];
__device__ float g_sg[NTOK];
__device__ int   g_top[NTOK * 2];
__device__ int   g_cnt[NE];
__device__ int   g_list[NE * NTOK];
__device__ float g_acte[(size_t)NE * NTOK * FE];   // per-expert act scratch
__device__ float g_acts[(size_t)NTOK * FS];        // shared-expert act scratch

// ---------------- helpers ----------------
__device__ __forceinline__ uint32_t f2tf(float x) {
    uint32_t r;
    asm("cvt.rna.tf32.f32 %0, %1;" : "=r"(r) : "f"(x));
    return r;
}

__device__ __forceinline__ void mma8(float* c, const uint32_t* a, const uint32_t* b) {
    asm volatile(
        "mma.sync.aligned.m16n8k8.row.col.f32.tf32.tf32.f32 "
        "{%0,%1,%2,%3},{%4,%5,%6,%7},{%8,%9},{%0,%1,%2,%3};"
        : "+f"(c[0]), "+f"(c[1]), "+f"(c[2]), "+f"(c[3])
        : "r"(a[0]), "r"(a[1]), "r"(a[2]), "r"(a[3]), "r"(b[0]), "r"(b[1]));
}

// ---------------- 1. router: logits -> top2 weights, shared gate ----------------
__global__ void router_kernel(const float* __restrict__ h,
                              const float* __restrict__ gw,
                              const float* __restrict__ wsg) {
    int lane = threadIdx.x & 31;
    int t = blockIdx.x * (blockDim.x >> 5) + (threadIdx.x >> 5);
    if (t >= NTOK) return;
    const float* hr = h + (size_t)t * DM;
    float acc[8];
#pragma unroll
    for (int i = 0; i < 8; i++) acc[i] = 0.f;
    float as_ = 0.f;
    for (int d = lane; d < DM; d += 32) {
        float hv = hr[d];
        const float4* gr = reinterpret_cast<const float4*>(gw + (size_t)d * NE);
        float4 g0 = gr[0], g1 = gr[1];
        acc[0] += hv * g0.x; acc[1] += hv * g0.y; acc[2] += hv * g0.z; acc[3] += hv * g0.w;
        acc[4] += hv * g1.x; acc[5] += hv * g1.y; acc[6] += hv * g1.z; acc[7] += hv * g1.w;
        as_ += hv * wsg[d];
    }
#pragma unroll
    for (int o = 16; o; o >>= 1) {
#pragma unroll
        for (int i = 0; i < 8; i++) acc[i] += __shfl_xor_sync(0xffffffffu, acc[i], o);
        as_ += __shfl_xor_sync(0xffffffffu, as_, o);
    }
    if (lane == 0) {
        int i1 = 0;
#pragma unroll
        for (int e = 1; e < 8; e++) if (acc[e] > acc[i1]) i1 = e;
        int i2 = -1;
#pragma unroll
        for (int e = 0; e < 8; e++) {
            if (e == i1) continue;
            if (i2 < 0 || acc[e] > acc[i2]) i2 = e;
        }
        // normalized top2 softmax weights: e^{l1}/(e^{l1}+e^{l2})
        float e2 = __expf(acc[i2] - acc[i1]);
        float w1 = 1.f / (1.f + e2);
        float w2 = e2 / (1.f + e2);
#pragma unroll
        for (int e = 0; e < 8; e++)
            g_comb[t * NE + e] = (e == i1) ? w1 : ((e == i2) ? w2 : 0.f);
        g_top[t * 2] = i1;
        g_top[t * 2 + 1] = i2;
        g_sg[t] = 1.f / (1.f + __expf(-as_));
    }
}

// ---------------- 2. deterministic per-expert token lists ----------------
__global__ void build_lists_kernel() {
    int e = blockIdx.x;
    int tid = threadIdx.x;
    __shared__ int warp_cnt[8];
    __shared__ int s_base;
    if (tid == 0) s_base = 0;
    __syncthreads();
    for (int base = 0; base < NTOK; base += 256) {
        int t = base + tid;
        int flag = (g_top[t * 2] == e) || (g_top[t * 2 + 1] == e);
        unsigned bal = __ballot_sync(0xffffffffu, flag);
        int lane = tid & 31, w = tid >> 5;
        if (lane == 0) warp_cnt[w] = __popc(bal);
        __syncthreads();
        int off = 0;
        for (int i = 0; i < w; i++) off += warp_cnt[i];
        int pos = s_base + off + __popc(bal & ((1u << lane) - 1u));
        if (flag) g_list[e * NTOK + pos] = t;
        __syncthreads();
        if (tid == 0) {
            int tot = 0;
            for (int i = 0; i < 8; i++) tot += warp_cnt[i];
            s_base += tot;
        }
        __syncthreads();
    }
    if (tid == 0) g_cnt[e] = s_base;
}

// ---------------- 3. dual-B GEMM (gate & up) with silu(g)*u epilogue ----------------
// C[M, N] tile BM=128 x BN=64, BK=16, 256 threads, warps 4(m) x 2(n), warp tile 32x32.
template <bool EXPERT>
__global__ void gemm1_kernel(const float* __restrict__ A,
                             const float* __restrict__ Bg,
                             const float* __restrict__ Bu) {
    const int BK = 16, BM = 128, BN = 64;
    const int ldb = EXPERT ? FE : FS;
    const int ldc = ldb;
    __shared__ uint32_t As[BK][BM + 4];
    __shared__ uint32_t B1s[BK][BN + 4];
    __shared__ uint32_t B2s[BK][BN + 4];

    int e = EXPERT ? blockIdx.z : 0;
    int M = EXPERT ? g_cnt[e] : NTOK;
    int row0 = blockIdx.y * BM;
    if (row0 >= M) return;
    const int* rl = g_list + e * NTOK;
    const float* B1 = Bg + (EXPERT ? (size_t)e * DM * FE : 0);
    const float* B2 = Bu + (EXPERT ? (size_t)e * DM * FE : 0);
    float* C = EXPERT ? (g_acte + (size_t)e * NTOK * FE) : g_acts;
    int n0 = blockIdx.x * BN;

    int tid = threadIdx.x;
    int lane = tid & 31, wid = tid >> 5;
    int wm = (wid >> 1) * 32, wn = (wid & 1) * 32;
    int grp = lane >> 2, tg = lane & 3;

    float c1[2][4][4], c2[2][4][4];
#pragma unroll
    for (int i = 0; i < 2; i++)
#pragma unroll
        for (int j = 0; j < 4; j++)
#pragma unroll
            for (int k = 0; k < 4; k++) { c1[i][j][k] = 0.f; c2[i][j][k] = 0.f; }

    int ar = tid >> 2, akq = tid & 3;        // A staging: 64 rows/pass, 4 thr/row
    int bkr = tid >> 4, bc = (tid & 15) * 4; // B staging: 16 k-rows, 16 thr/row

    for (int k0 = 0; k0 < DM; k0 += BK) {
#pragma unroll
        for (int p = 0; p < 2; p++) {
            int m = p * 64 + ar;
            int r = row0 + m;
            float4 v = make_float4(0.f, 0.f, 0.f, 0.f);
            if (r < M) {
                int sr = EXPERT ? rl[r] : r;
                v = *reinterpret_cast<const float4*>(A + (size_t)sr * DM + k0 + akq * 4);
            }
            As[akq * 4 + 0][m] = f2tf(v.x);
            As[akq * 4 + 1][m] = f2tf(v.y);
            As[akq * 4 + 2][m] = f2tf(v.z);
            As[akq * 4 + 3][m] = f2tf(v.w);
        }
        {
            float4 v1 = *reinterpret_cast<const float4*>(B1 + (size_t)(k0 + bkr) * ldb + n0 + bc);
            float4 v2 = *reinterpret_cast<const float4*>(B2 + (size_t)(k0 + bkr) * ldb + n0 + bc);
            *reinterpret_cast<uint4*>(&B1s[bkr][bc]) =
                make_uint4(f2tf(v1.x), f2tf(v1.y), f2tf(v1.z), f2tf(v1.w));
            *reinterpret_cast<uint4*>(&B2s[bkr][bc]) =
                make_uint4(f2tf(v2.x), f2tf(v2.y), f2tf(v2.z), f2tf(v2.w));
        }
        __syncthreads();
#pragma unroll
        for (int ks = 0; ks < BK; ks += 8) {
            uint32_t a[2][4];
#pragma unroll
            for (int im = 0; im < 2; im++) {
                int mb = wm + im * 16;
                a[im][0] = As[ks + tg][mb + grp];
                a[im][1] = As[ks + tg][mb + 8 + grp];
                a[im][2] = As[ks + tg + 4][mb + grp];
                a[im][3] = As[ks + tg + 4][mb + 8 + grp];
            }
#pragma unroll
            for (int in = 0; in < 4; in++) {
                int nb = wn + in * 8 + grp;
                uint32_t b1[2] = { B1s[ks + tg][nb], B1s[ks + tg + 4][nb] };
                uint32_t b2[2] = { B2s[ks + tg][nb], B2s[ks + tg + 4][nb] };
#pragma unroll
                for (int im = 0; im < 2; im++) {
                    mma8(c1[im][in], a[im], b1);
                    mma8(c2[im][in], a[im], b2);
                }
            }
        }
        __syncthreads();
    }
    // epilogue: silu(gate) * up
#pragma unroll
    for (int im = 0; im < 2; im++) {
#pragma unroll
        for (int in = 0; in < 4; in++) {
#pragma unroll
            for (int j = 0; j < 4; j++) {
                int r = row0 + wm + im * 16 + grp + ((j >= 2) ? 8 : 0);
                int cc = n0 + wn + in * 8 + 2 * tg + (j & 1);
                if (r < M) {
                    float g = c1[im][in][j], u = c2[im][in][j];
                    float act = g * (1.f / (1.f + __expf(-g))) * u;
                    C[(size_t)r * ldc + cc] = act;
                }
            }
        }
    }
}

// ---------------- 4. down-proj GEMM: shared (store) / expert (atomic scatter) ---
// BM=128 x BN=128, BK=16, 256 threads, warps 4(m) x 2(n), warp tile 32x64.
template <bool EXPERT>
__global__ void gemm2_kernel(const float* __restrict__ Bd, float* __restrict__ out) {
    const int BK = 16, BM = 128, BN = 128;
    const int K = EXPERT ? FE : FS;
    __shared__ uint32_t As[BK][BM + 4];
    __shared__ uint32_t Bs[BK][BN + 4];

    int e = EXPERT ? blockIdx.z : 0;
    int M = EXPERT ? g_cnt[e] : NTOK;
    int row0 = blockIdx.y * BM;
    if (row0 >= M) return;
    const float* Aact = EXPERT ? (g_acte + (size_t)e * NTOK * FE) : g_acts;
    const float* B = Bd + (EXPERT ? (size_t)e * FE * DM : 0);
    const int* rl = g_list + e * NTOK;
    int n0 = blockIdx.x * BN;

    int tid = threadIdx.x;
    int lane = tid & 31, wid = tid >> 5;
    int wm = (wid >> 1) * 32, wn = (wid & 1) * 64;
    int grp = lane >> 2, tg = lane & 3;

    float c[2][8][4];
#pragma unroll
    for (int i = 0; i < 2; i++)
#pragma unroll
        for (int j = 0; j < 8; j++)
#pragma unroll
            for (int k = 0; k < 4; k++) c[i][j][k] = 0.f;

    int ar = tid >> 2, akq = tid & 3;
    int bkr = tid >> 5, bc = (tid & 31) * 4; // B staging: 8 k-rows/pass, 32 thr/row

    for (int k0 = 0; k0 < K; k0 += BK) {
#pragma unroll
        for (int p = 0; p < 2; p++) {
            int m = p * 64 + ar;
            int r = row0 + m;
            float4 v = make_float4(0.f, 0.f, 0.f, 0.f);
            if (r < M)
                v = *reinterpret_cast<const float4*>(Aact + (size_t)r * K + k0 + akq * 4);
            As[akq * 4 + 0][m] = f2tf(v.x);
            As[akq * 4 + 1][m] = f2tf(v.y);
            As[akq * 4 + 2][m] = f2tf(v.z);
            As[akq * 4 + 3][m] = f2tf(v.w);
        }
#pragma unroll
        for (int p = 0; p < 2; p++) {
            int kk = p * 8 + bkr;
            float4 v = *reinterpret_cast<const float4*>(B + (size_t)(k0 + kk) * DM + n0 + bc);
            *reinterpret_cast<uint4*>(&Bs[kk][bc]) =
                make_uint4(f2tf(v.x), f2tf(v.y), f2tf(v.z), f2tf(v.w));
        }
        __syncthreads();
#pragma unroll
        for (int ks = 0; ks < BK; ks += 8) {
            uint32_t a[2][4];
#pragma unroll
            for (int im = 0; im < 2; im++) {
                int mb = wm + im * 16;
                a[im][0] = As[ks + tg][mb + grp];
                a[im][1] = As[ks + tg][mb + 8 + grp];
                a[im][2] = As[ks + tg + 4][mb + grp];
                a[im][3] = As[ks + tg + 4][mb + 8 + grp];
            }
#pragma unroll
            for (int in = 0; in < 8; in++) {
                int nb = wn + in * 8 + grp;
                uint32_t b[2] = { Bs[ks + tg][nb], Bs[ks + tg + 4][nb] };
#pragma unroll
                for (int im = 0; im < 2; im++) mma8(c[im][in], a[im], b);
            }
        }
        __syncthreads();
    }
#pragma unroll
    for (int im = 0; im < 2; im++) {
#pragma unroll
        for (int in = 0; in < 8; in++) {
#pragma unroll
            for (int j = 0; j < 4; j++) {
                int r = row0 + wm + im * 16 + grp + ((j >= 2) ? 8 : 0);
                int cc = n0 + wn + in * 8 + 2 * tg + (j & 1);
                if (r < M) {
                    if (EXPERT) {
                        int tok = rl[r];
                        float s = g_comb[tok * NE + e];
                        atomicAdd(&out[(size_t)tok * DM + cc], s * c[im][in][j]);
                    } else {
                        out[(size_t)r * DM + cc] = g_sg[r] * c[im][in][j];
                    }
                }
            }
        }
    }
}

// ---------------- launch ----------------
extern "C" void kernel_launch(void* const* d_in, const int* in_sizes, int n_in,
                              void* d_out, int out_size) {
    const float* h       = (const float*)d_in[0];
    const float* gate_w  = (const float*)d_in[1];
    const float* w_gate  = (const float*)d_in[2];
    const float* w_up    = (const float*)d_in[3];
    const float* w_down  = (const float*)d_in[4];
    const float* ws_gate = (const float*)d_in[5];
    const float* ws_up   = (const float*)d_in[6];
    const float* ws_down = (const float*)d_in[7];
    const float* wsg     = (const float*)d_in[8];
    float* out = (float*)d_out;

    router_kernel<<<NTOK / 8, 256>>>(h, gate_w, wsg);
    build_lists_kernel<<<NE, 256>>>();

    // shared expert: act_s = silu(h@ws_gate)*(h@ws_up)
    gemm1_kernel<false><<<dim3(FS / 64, NTOK / 128), 256>>>(h, ws_gate, ws_up);
    // routed experts: act_e = silu(Xe@Wg)*(Xe@Wu)  (gathered rows, early-exit)
    gemm1_kernel<true><<<dim3(FE / 64, NTOK / 128, NE), 256>>>(h, w_gate, w_up);

    // out = sigmoid(h@wsg) * (act_s @ ws_down)   (plain store, initializes out)
    gemm2_kernel<false><<<dim3(DM / 128, NTOK / 128), 256>>>(ws_down, out);
    // out += comb[t,e] * (act_e @ Wd[e])         (atomic scatter-add)
    gemm2_kernel<true><<<dim3(DM / 128, NTOK / 128, NE), 256>>>(w_down, out);
}

// round 2
// speedup vs baseline: 1.2097x; 1.2097x over previous
#include <cuda_runtime.h>
#include <stdint.h>

#define NTOK 8192
#define DM   2048
#define NE   8
#define FE   1024
#define FS   2048

// ---------------- scratch (device globals; no allocation) ----------------
__device__ float g_comb[NTOK * NE];
__device__ float g_sg[NTOK];
__device__ int   g_top[NTOK * 2];
__device__ int   g_cnt[NE];
__device__ int   g_list[NE * NTOK];
__device__ float g_acte[(size_t)NE * NTOK * FE];   // per-expert act scratch
__device__ float g_acts[(size_t)NTOK * FS];        // shared-expert act scratch

// ---------------- helpers ----------------
__device__ __forceinline__ uint32_t f2tf(float x) {
    uint32_t r;
    asm("cvt.rna.tf32.f32 %0, %1;" : "=r"(r) : "f"(x));
    return r;
}

__device__ __forceinline__ void mma8(float* c, const uint32_t* a, const uint32_t* b) {
    asm volatile(
        "mma.sync.aligned.m16n8k8.row.col.f32.tf32.tf32.f32 "
        "{%0,%1,%2,%3},{%4,%5,%6,%7},{%8,%9},{%0,%1,%2,%3};"
        : "+f"(c[0]), "+f"(c[1]), "+f"(c[2]), "+f"(c[3])
        : "r"(a[0]), "r"(a[1]), "r"(a[2]), "r"(a[3]), "r"(b[0]), "r"(b[1]));
}

// bank swizzle: XOR column bits [3:4] with k-dependent pattern.
// Reads (k = ks+tg / ks+tg+4, col = tile+grp): conflict-free.
// A staging stores: conflict-free. B staging stores: <=2-way.
__device__ __forceinline__ int swz(int k) {
    return ((k & 3) ^ ((k >> 2) & 3)) << 3;
}

// ---------------- 1. router ----------------
__global__ void router_kernel(const float* __restrict__ h,
                              const float* __restrict__ gw,
                              const float* __restrict__ wsg) {
    int lane = threadIdx.x & 31;
    int t = blockIdx.x * (blockDim.x >> 5) + (threadIdx.x >> 5);
    if (t >= NTOK) return;
    const float* hr = h + (size_t)t * DM;
    float acc[8];
#pragma unroll
    for (int i = 0; i < 8; i++) acc[i] = 0.f;
    float as_ = 0.f;
    for (int d = lane; d < DM; d += 32) {
        float hv = hr[d];
        const float4* gr = reinterpret_cast<const float4*>(gw + (size_t)d * NE);
        float4 g0 = gr[0], g1 = gr[1];
        acc[0] += hv * g0.x; acc[1] += hv * g0.y; acc[2] += hv * g0.z; acc[3] += hv * g0.w;
        acc[4] += hv * g1.x; acc[5] += hv * g1.y; acc[6] += hv * g1.z; acc[7] += hv * g1.w;
        as_ += hv * wsg[d];
    }
#pragma unroll
    for (int o = 16; o; o >>= 1) {
#pragma unroll
        for (int i = 0; i < 8; i++) acc[i] += __shfl_xor_sync(0xffffffffu, acc[i], o);
        as_ += __shfl_xor_sync(0xffffffffu, as_, o);
    }
    if (lane == 0) {
        int i1 = 0;
#pragma unroll
        for (int e = 1; e < 8; e++) if (acc[e] > acc[i1]) i1 = e;
        int i2 = -1;
#pragma unroll
        for (int e = 0; e < 8; e++) {
            if (e == i1) continue;
            if (i2 < 0 || acc[e] > acc[i2]) i2 = e;
        }
        float e2 = __expf(acc[i2] - acc[i1]);
        float w1 = 1.f / (1.f + e2);
        float w2 = e2 / (1.f + e2);
#pragma unroll
        for (int e = 0; e < 8; e++)
            g_comb[t * NE + e] = (e == i1) ? w1 : ((e == i2) ? w2 : 0.f);
        g_top[t * 2] = i1;
        g_top[t * 2 + 1] = i2;
        g_sg[t] = 1.f / (1.f + __expf(-as_));
    }
}

// ---------------- 2. deterministic per-expert token lists ----------------
__global__ void build_lists_kernel() {
    int e = blockIdx.x;
    int tid = threadIdx.x;
    __shared__ int warp_cnt[8];
    __shared__ int s_base;
    if (tid == 0) s_base = 0;
    __syncthreads();
    for (int base = 0; base < NTOK; base += 256) {
        int t = base + tid;
        int flag = (g_top[t * 2] == e) || (g_top[t * 2 + 1] == e);
        unsigned bal = __ballot_sync(0xffffffffu, flag);
        int lane = tid & 31, w = tid >> 5;
        if (lane == 0) warp_cnt[w] = __popc(bal);
        __syncthreads();
        int off = 0;
        for (int i = 0; i < w; i++) off += warp_cnt[i];
        int pos = s_base + off + __popc(bal & ((1u << lane) - 1u));
        if (flag) g_list[e * NTOK + pos] = t;
        __syncthreads();
        if (tid == 0) {
            int tot = 0;
            for (int i = 0; i < 8; i++) tot += warp_cnt[i];
            s_base += tot;
        }
        __syncthreads();
    }
    if (tid == 0) g_cnt[e] = s_base;
}

// ---------------- 3. dual-B GEMM (gate & up), silu epilogue ----------------
// BM=128 x BN=128, BK=16, 256 thr, warps 2(m)x4(n), warp tile 64x32 per matrix.
// Double-buffered smem, XOR-swizzled, register-prefetched gmem.

#define G1_LDG(K0)                                                               \
    {                                                                            \
        int _k0 = (K0);                                                          \
        _Pragma("unroll") for (int p = 0; p < 2; p++) {                          \
            va[p] = rv[p]                                                        \
                ? *(const float4*)(A + (size_t)sr[p] * DM + _k0 + aq * 4)        \
                : make_float4(0.f, 0.f, 0.f, 0.f);                               \
            vb1[p] = *(const float4*)(B1 + (size_t)(_k0 + bk) * ldb + n0 + p * 64 + bq * 4); \
            vb2[p] = *(const float4*)(B2 + (size_t)(_k0 + bk) * ldb + n0 + p * 64 + bq * 4); \
        }                                                                        \
    }

#define G1_STS(BUF)                                                              \
    {                                                                            \
        int _b = (BUF);                                                          \
        _Pragma("unroll") for (int p = 0; p < 2; p++) {                          \
            const float* fv = &va[p].x;                                          \
            const float* f1 = &vb1[p].x;                                         \
            const float* f2 = &vb2[p].x;                                         \
            _Pragma("unroll") for (int i = 0; i < 4; i++) {                      \
                As[_b][aoff[p][i]]  = f2tf(fv[i]);                               \
                B1s[_b][boff[p][i]] = f2tf(f1[i]);                               \
                B2s[_b][boff[p][i]] = f2tf(f2[i]);                               \
            }                                                                    \
        }                                                                        \
    }

template <bool EXPERT>
__global__ __launch_bounds__(256, 1)
void gemm1_kernel(const float* __restrict__ A,
                  const float* __restrict__ Bg,
                  const float* __restrict__ Bu) {
    const int BK = 16, BM = 128, BN = 128;
    const int ldb = EXPERT ? FE : FS;
    __shared__ uint32_t As[2][BK * BM];
    __shared__ uint32_t B1s[2][BK * BN];
    __shared__ uint32_t B2s[2][BK * BN];

    int e = EXPERT ? blockIdx.z : 0;
    int M = EXPERT ? g_cnt[e] : NTOK;
    int row0 = blockIdx.y * BM;
    if (row0 >= M) return;
    const int* rl = g_list + e * NTOK;
    const float* B1 = Bg + (EXPERT ? (size_t)e * DM * FE : 0);
    const float* B2 = Bu + (EXPERT ? (size_t)e * DM * FE : 0);
    float* C = EXPERT ? (g_acte + (size_t)e * NTOK * FE) : g_acts;
    int n0 = blockIdx.x * BN;

    int tid = threadIdx.x, lane = tid & 31, wid = tid >> 5;
    int wmt = (wid >> 2) * 4;   // base m-tile (16 rows each)
    int wnt = (wid & 3) * 4;    // base n-tile (8 cols each)
    int grp = lane >> 2, tg = lane & 3;

    // staging thread mapping
    int ar = tid >> 2, aq = tid & 3;     // A: row, k-quad
    int bk = tid >> 4, bq = tid & 15;    // B: k-row, n-quad
    int aoff[2][4], boff[2][4];
#pragma unroll
    for (int p = 0; p < 2; p++)
#pragma unroll
        for (int i = 0; i < 4; i++) {
            int k = aq * 4 + i;
            aoff[p][i] = k * BM + ((p * 64 + ar) ^ swz(k));
            boff[p][i] = bk * BN + ((p * 64 + bq * 4 + i) ^ swz(bk));
        }
    int sr[2]; bool rv[2];
#pragma unroll
    for (int p = 0; p < 2; p++) {
        int r = row0 + p * 64 + ar;
        rv[p] = r < M;
        sr[p] = rv[p] ? (EXPERT ? rl[r] : r) : 0;
    }

    float c1[4][4][4], c2[4][4][4];
#pragma unroll
    for (int i = 0; i < 4; i++)
#pragma unroll
        for (int j = 0; j < 4; j++)
#pragma unroll
            for (int q = 0; q < 4; q++) { c1[i][j][q] = 0.f; c2[i][j][q] = 0.f; }

    float4 va[2], vb1[2], vb2[2];
    const int T = DM / BK;

    G1_LDG(0)
    G1_STS(0)
    __syncthreads();

    for (int t = 0; t < T; t++) {
        int cur = t & 1;
        if (t + 1 < T) G1_LDG((t + 1) * BK)
        const uint32_t* Ab = As[cur];
        const uint32_t* B1b = B1s[cur];
        const uint32_t* B2b = B2s[cur];
#pragma unroll
        for (int kt = 0; kt < 2; kt++) {
            int ks = kt * 8;
            int kA = ks + tg, kB = ks + tg + 4;
            int sA = swz(kA), sB = swz(kB);
            uint32_t a[4][4], b1[4][2], b2[4][2];
#pragma unroll
            for (int im = 0; im < 4; im++) {
                int mb = (wmt + im) * 16;
                a[im][0] = Ab[kA * BM + ((mb + grp) ^ sA)];
                a[im][1] = Ab[kA * BM + ((mb + 8 + grp) ^ sA)];
                a[im][2] = Ab[kB * BM + ((mb + grp) ^ sB)];
                a[im][3] = Ab[kB * BM + ((mb + 8 + grp) ^ sB)];
            }
#pragma unroll
            for (int in = 0; in < 4; in++) {
                int nb = (wnt + in) * 8 + grp;
                int o0 = kA * BN + (nb ^ sA);
                int o1 = kB * BN + (nb ^ sB);
                b1[in][0] = B1b[o0]; b1[in][1] = B1b[o1];
                b2[in][0] = B2b[o0]; b2[in][1] = B2b[o1];
            }
#pragma unroll
            for (int im = 0; im < 4; im++)
#pragma unroll
                for (int in = 0; in < 4; in++) {
                    mma8(c1[im][in], a[im], b1[in]);
                    mma8(c2[im][in], a[im], b2[in]);
                }
        }
        if (t + 1 < T) G1_STS((t + 1) & 1)
        __syncthreads();
    }

    // epilogue: silu(gate) * up, float2 stores
#pragma unroll
    for (int im = 0; im < 4; im++) {
        int r = row0 + (wmt + im) * 16 + grp;
#pragma unroll
        for (int in = 0; in < 4; in++) {
            int cc = n0 + (wnt + in) * 8 + 2 * tg;
            if (r < M) {
                float g0 = c1[im][in][0], u0 = c2[im][in][0];
                float g1 = c1[im][in][1], u1 = c2[im][in][1];
                float2 o;
                o.x = g0 * (1.f / (1.f + __expf(-g0))) * u0;
                o.y = g1 * (1.f / (1.f + __expf(-g1))) * u1;
                *reinterpret_cast<float2*>(&C[(size_t)r * ldb + cc]) = o;
            }
            if (r + 8 < M) {
                float g0 = c1[im][in][2], u0 = c2[im][in][2];
                float g1 = c1[im][in][3], u1 = c2[im][in][3];
                float2 o;
                o.x = g0 * (1.f / (1.f + __expf(-g0))) * u0;
                o.y = g1 * (1.f / (1.f + __expf(-g1))) * u1;
                *reinterpret_cast<float2*>(&C[(size_t)(r + 8) * ldb + cc]) = o;
            }
        }
    }
}

// ---------------- 4. down-proj GEMM ----------------
// BM=128 x BN=256, BK=16, 256 thr, warps 2(m)x4(n), warp tile 64x64.

#define G2_LDG(K0)                                                               \
    {                                                                            \
        int _k0 = (K0);                                                          \
        _Pragma("unroll") for (int p = 0; p < 2; p++) {                          \
            va[p] = rv[p]                                                        \
                ? *(const float4*)(Aact + (size_t)(row0 + p * 64 + ar) * K + _k0 + aq * 4) \
                : make_float4(0.f, 0.f, 0.f, 0.f);                               \
        }                                                                        \
        _Pragma("unroll") for (int p = 0; p < 4; p++) {                          \
            vb[p] = *(const float4*)(B + (size_t)(_k0 + bk) * DM + n0 + p * 64 + bq * 4); \
        }                                                                        \
    }

#define G2_STS(BUF)                                                              \
    {                                                                            \
        int _b = (BUF);                                                          \
        _Pragma("unroll") for (int p = 0; p < 2; p++) {                          \
            const float* fv = &va[p].x;                                          \
            _Pragma("unroll") for (int i = 0; i < 4; i++)                        \
                As[_b][aoff[p][i]] = f2tf(fv[i]);                                \
        }                                                                        \
        _Pragma("unroll") for (int p = 0; p < 4; p++) {                          \
            const float* fb = &vb[p].x;                                          \
            _Pragma("unroll") for (int i = 0; i < 4; i++)                        \
                Bs[_b][boff[p][i]] = f2tf(fb[i]);                                \
        }                                                                        \
    }

template <bool EXPERT>
__global__ __launch_bounds__(256, 1)
void gemm2_kernel(const float* __restrict__ Bd, float* __restrict__ out) {
    const int BK = 16, BM = 128, BN = 256;
    const int K = EXPERT ? FE : FS;
    __shared__ uint32_t As[2][BK * BM];
    __shared__ uint32_t Bs[2][BK * BN];

    int e = EXPERT ? blockIdx.z : 0;
    int M = EXPERT ? g_cnt[e] : NTOK;
    int row0 = blockIdx.y * BM;
    if (row0 >= M) return;
    const float* Aact = EXPERT ? (g_acte + (size_t)e * NTOK * FE) : g_acts;
    const float* B = Bd + (EXPERT ? (size_t)e * FE * DM : 0);
    const int* rl = g_list + e * NTOK;
    int n0 = blockIdx.x * BN;

    int tid = threadIdx.x, lane = tid & 31, wid = tid >> 5;
    int wmt = (wid >> 2) * 4;   // 4 m-tiles of 16
    int wnt = (wid & 3) * 8;    // 8 n-tiles of 8
    int grp = lane >> 2, tg = lane & 3;

    int ar = tid >> 2, aq = tid & 3;
    int bk = tid >> 4, bq = tid & 15;
    int aoff[2][4], boff[4][4];
#pragma unroll
    for (int i = 0; i < 4; i++) {
        int k = aq * 4 + i;
#pragma unroll
        for (int p = 0; p < 2; p++)
            aoff[p][i] = k * BM + ((p * 64 + ar) ^ swz(k));
#pragma unroll
        for (int p = 0; p < 4; p++)
            boff[p][i] = bk * BN + ((p * 64 + bq * 4 + i) ^ swz(bk));
    }
    bool rv[2];
#pragma unroll
    for (int p = 0; p < 2; p++) rv[p] = (row0 + p * 64 + ar) < M;

    float c[4][8][4];
#pragma unroll
    for (int i = 0; i < 4; i++)
#pragma unroll
        for (int j = 0; j < 8; j++)
#pragma unroll
            for (int q = 0; q < 4; q++) c[i][j][q] = 0.f;

    float4 va[2], vb[4];
    const int T = K / BK;

    G2_LDG(0)
    G2_STS(0)
    __syncthreads();

    for (int t = 0; t < T; t++) {
        int cur = t & 1;
        if (t + 1 < T) G2_LDG((t + 1) * BK)
        const uint32_t* Ab = As[cur];
        const uint32_t* Bb = Bs[cur];
#pragma unroll
        for (int kt = 0; kt < 2; kt++) {
            int ks = kt * 8;
            int kA = ks + tg, kB = ks + tg + 4;
            int sA = swz(kA), sB = swz(kB);
            uint32_t a[4][4], b[8][2];
#pragma unroll
            for (int im = 0; im < 4; im++) {
                int mb = (wmt + im) * 16;
                a[im][0] = Ab[kA * BM + ((mb + grp) ^ sA)];
                a[im][1] = Ab[kA * BM + ((mb + 8 + grp) ^ sA)];
                a[im][2] = Ab[kB * BM + ((mb + grp) ^ sB)];
                a[im][3] = Ab[kB * BM + ((mb + 8 + grp) ^ sB)];
            }
#pragma unroll
            for (int in = 0; in < 8; in++) {
                int nb = (wnt + in) * 8 + grp;
                b[in][0] = Bb[kA * BN + (nb ^ sA)];
                b[in][1] = Bb[kB * BN + (nb ^ sB)];
            }
#pragma unroll
            for (int im = 0; im < 4; im++)
#pragma unroll
                for (int in = 0; in < 8; in++)
                    mma8(c[im][in], a[im], b[in]);
        }
        if (t + 1 < T) G2_STS((t + 1) & 1)
        __syncthreads();
    }

    // epilogue
#pragma unroll
    for (int im = 0; im < 4; im++) {
        int r = row0 + (wmt + im) * 16 + grp;
        int tok0 = 0, tok1 = 0;
        float s0 = 0.f, s1 = 0.f;
        if (EXPERT) {
            if (r < M)     { tok0 = rl[r];     s0 = g_comb[tok0 * NE + e]; }
            if (r + 8 < M) { tok1 = rl[r + 8]; s1 = g_comb[tok1 * NE + e]; }
        } else {
            if (r < M)     s0 = g_sg[r];
            if (r + 8 < M) s1 = g_sg[r + 8];
        }
#pragma unroll
        for (int in = 0; in < 8; in++) {
            int cc = n0 + (wnt + in) * 8 + 2 * tg;
            if (r < M) {
                if (EXPERT) {
                    atomicAdd(&out[(size_t)tok0 * DM + cc],     s0 * c[im][in][0]);
                    atomicAdd(&out[(size_t)tok0 * DM + cc + 1], s0 * c[im][in][1]);
                } else {
                    float2 o; o.x = s0 * c[im][in][0]; o.y = s0 * c[im][in][1];
                    *reinterpret_cast<float2*>(&out[(size_t)r * DM + cc]) = o;
                }
            }
            if (r + 8 < M) {
                if (EXPERT) {
                    atomicAdd(&out[(size_t)tok1 * DM + cc],     s1 * c[im][in][2]);
                    atomicAdd(&out[(size_t)tok1 * DM + cc + 1], s1 * c[im][in][3]);
                } else {
                    float2 o; o.x = s1 * c[im][in][2]; o.y = s1 * c[im][in][3];
                    *reinterpret_cast<float2*>(&out[(size_t)(r + 8) * DM + cc]) = o;
                }
            }
        }
    }
}

// ---------------- launch ----------------
extern "C" void kernel_launch(void* const* d_in, const int* in_sizes, int n_in,
                              void* d_out, int out_size) {
    const float* h       = (const float*)d_in[0];
    const float* gate_w  = (const float*)d_in[1];
    const float* w_gate  = (const float*)d_in[2];
    const float* w_up    = (const float*)d_in[3];
    const float* w_down  = (const float*)d_in[4];
    const float* ws_gate = (const float*)d_in[5];
    const float* ws_up   = (const float*)d_in[6];
    const float* ws_down = (const float*)d_in[7];
    const float* wsg     = (const float*)d_in[8];
    float* out = (float*)d_out;

    router_kernel<<<NTOK / 8, 256>>>(h, gate_w, wsg);
    build_lists_kernel<<<NE, 256>>>();

    // shared expert: act_s = silu(h@ws_gate)*(h@ws_up)
    gemm1_kernel<false><<<dim3(FS / 128, NTOK / 128), 256>>>(h, ws_gate, ws_up);
    // routed experts: act_e = silu(Xe@Wg)*(Xe@Wu)
    gemm1_kernel<true><<<dim3(FE / 128, NTOK / 128, NE), 256>>>(h, w_gate, w_up);

    // out = sigmoid(h@wsg) * (act_s @ ws_down)
    gemm2_kernel<false><<<dim3(DM / 256, NTOK / 128), 256>>>(ws_down, out);
    // out += comb[t,e] * (act_e @ Wd[e])
    gemm2_kernel<true><<<dim3(DM / 256, NTOK / 128, NE), 256>>>(w_down, out);
}